// round 1
// baseline (speedup 1.0000x reference)
#include <cuda_runtime.h>
#include <math.h>
#include <stdint.h>

#define NB 16
#define NP 512
#define NR (NB*NP)      // 8192 rows
#define NV 20           // LANE_LEN
#define NC 128          // C
#define NT 64           // T
#define NH 192          // H
#define N_TL 9
#define N_LT 20
#define NDEPTH 3

// shared layout (floats)
#define OFF_SF   0
#define OFF_SY   8192
#define OFF_WB   16384
#define OFF_SG   20480      // 80 floats: geom g[v][4]
#define OFF_SRED 20560      // 8 floats
#define OFF_SIDX 20568      // 64 ints (tl[20], lt[20], maskv[20], mask_p)
#define SMEM_FLOATS 20632
#define SMEM_BYTES (SMEM_FLOATS*4)

struct Params {
  const float* x;
  const float* tl_table; const float* lane_table;
  const float* ch1w; const float* ch1b; const float* ch2w; const float* ch2b;
  const float* tk1w; const float* tk1b; const float* tk2w; const float* tk2b;
  const float* bn1w; const float* bn1b;
  const float* bt1w; const float* bt1b; const float* bt2w; const float* bt2b;
  const float* bn2w; const float* bn2b;
  const float* bc1w; const float* bc1b; const float* bc2w; const float* bc2b;
  const float* nw;  const float* nb;
  const float* e1w; const float* e1b; const float* e2w; const float* e2b;
  float* out; float* mask_out; float* pos_out;
};

__device__ __forceinline__ float gelu_f(float v){
  return 0.5f * v * (1.0f + erff(v * 0.70710678118654752440f));
}

// cooperative copy of n4 float4s from global to shared weight buffer
__device__ __forceinline__ void stage_w(float* wb, const float* g, int tid, int n4){
  const float4* g4 = (const float4*)g;
  float4* s4 = (float4*)wb;
  for (int i = tid; i < n4; i += 128) s4[i] = g4[i];
}

// acc[i][j] += sum_k A[k*NC + lane+32j] * W[k*NT + warp*16+i]
// (free dims: 64 "n" over warps, 128 "c" over lanes; K-major A in shared)
template<int K>
__device__ __forceinline__ void gemm_cu(const float* A, const float* W,
                                        float acc[16][4], int lane, int warp){
  #pragma unroll 4
  for (int k = 0; k < K; k++){
    float a[4];
    #pragma unroll
    for (int j = 0; j < 4; j++) a[j] = A[k*NC + lane + 32*j];
    #pragma unroll
    for (int i = 0; i < 16; i++){
      float w = W[k*NT + warp*16 + i];
      #pragma unroll
      for (int j = 0; j < 4; j++) acc[i][j] += a[j]*w;
    }
  }
}

// channel-mix tile: acc[i][j] += sum_{kk<32} A[(warp*16+i)*NC + k0+kk] * Wt[kk*NC + lane+32j]
__device__ __forceinline__ void gemm_tj_tile(const float* A, const float* Wt,
                                             float acc[16][4], int lane, int warp, int k0){
  #pragma unroll 4
  for (int kk = 0; kk < 32; kk++){
    float w[4];
    #pragma unroll
    for (int j = 0; j < 4; j++) w[j] = Wt[kk*NC + lane + 32*j];
    #pragma unroll
    for (int i = 0; i < 16; i++){
      float a = A[(warp*16+i)*NC + k0 + kk];
      #pragma unroll
      for (int j = 0; j < 4; j++) acc[i][j] += a * w[j];
    }
  }
}

__device__ __forceinline__ void zero_acc(float acc[16][4]){
  #pragma unroll
  for (int i = 0; i < 16; i++)
    #pragma unroll
    for (int j = 0; j < 4; j++) acc[i][j] = 0.f;
}

// LN over channel dim (128) per token; src/dst are [64][128] in shared
__device__ __forceinline__ void layernorm(const float* src, float* dst,
                                          const float wg[4], const float bg[4],
                                          int lane, int warp){
  for (int t = warp; t < NT; t += 4){
    float v[4];
    float s = 0.f, q = 0.f;
    #pragma unroll
    for (int j = 0; j < 4; j++){
      v[j] = src[t*NC + lane + 32*j];
      s += v[j]; q += v[j]*v[j];
    }
    #pragma unroll
    for (int o = 16; o > 0; o >>= 1){
      s += __shfl_xor_sync(0xffffffffu, s, o);
      q += __shfl_xor_sync(0xffffffffu, q, o);
    }
    float m  = s * (1.f/NC);
    float var = q * (1.f/NC) - m*m;
    float rs = rsqrtf(var + 1e-5f);
    #pragma unroll
    for (int j = 0; j < 4; j++)
      dst[t*NC + lane + 32*j] = (v[j]-m)*rs*wg[j] + bg[j];
  }
}

__global__ void __launch_bounds__(128)
lane_fusion_kernel(Params P){
  extern __shared__ float smem[];
  float* sf   = smem + OFF_SF;    // state f[t][c], 64x128
  float* sy   = smem + OFF_SY;    // scratch (LN out / intermediates)
  float* wb   = smem + OFF_WB;    // staged weight tile (<=4096 floats)
  float* sg   = smem + OFF_SG;    // geom [20][4]
  float* sred = smem + OFF_SRED;
  int*   sidx = (int*)(smem + OFF_SIDX);

  const int tid  = threadIdx.x;
  const int lane = tid & 31;
  const int warp = tid >> 5;
  const int r    = blockIdx.x;
  const float* xr = P.x + (size_t)r * (NV*5);

  // ---------------- preprocess: geom, indices, mask, pos ----------------
  if (tid < NV){
    float x0 = xr[tid*5+0], x1 = xr[tid*5+1], hg = xr[tid*5+2];
    float x3 = xr[tid*5+3], x4 = xr[tid*5+4];
    float ch = cosf(hg), sh = sinf(hg);
    sg[tid*4+0] = x0; sg[tid*4+1] = x1; sg[tid*4+2] = ch; sg[tid*4+3] = sh;
    int tl = (int)x3; tl = tl < 0 ? 0 : (tl > N_TL-1 ? N_TL-1 : tl);
    int lt = (int)x4; lt = lt < 0 ? 0 : (lt > N_LT-1 ? N_LT-1 : lt);
    sidx[tid]      = tl;
    sidx[NV+tid]   = lt;
    sidx[2*NV+tid] = (x0==0.f && x1==0.f && ch==0.f && sh==0.f) ? 1 : 0;
  }
  if (tid < 5){
    float mid = xr[(NV/2)*5 + tid];
    float sc = (tid==3) ? (1.f/(N_TL-1)) : ((tid==4) ? (1.f/(N_LT-1)) : 1.f);
    P.pos_out[(size_t)r*5 + tid] = mid * sc;
  }
  __syncthreads();
  if (tid == 0){
    int mp = 1;
    for (int v = 0; v < NV; v++) mp &= sidx[2*NV+v];
    sidx[3*NV] = mp;
    P.mask_out[r] = mp ? 1.f : 0.f;
  }

  // ---------------- stage 1a: h1[v][j] = gelu(g @ ch1w + b) -> sy[0..19] --
  {
    float w0 = P.ch1w[0*NC + tid];
    float w1 = P.ch1w[1*NC + tid];
    float w2 = P.ch1w[2*NC + tid];
    float w3 = P.ch1w[3*NC + tid];
    float b  = P.ch1b[tid];
    #pragma unroll
    for (int v = 0; v < NV; v++){
      float a = b + sg[v*4+0]*w0 + sg[v*4+1]*w1 + sg[v*4+2]*w2 + sg[v*4+3]*w3;
      sy[v*NC + tid] = gelu_f(a);
    }
  }
  __syncthreads();

  // ---------------- stage 1b: f0[v][c] = h1 @ ch2w + b2 + tables -> sf[0..19]
  {
    float acc[5][4];
    #pragma unroll
    for (int i = 0; i < 5; i++)
      #pragma unroll
      for (int j = 0; j < 4; j++) acc[i][j] = 0.f;
    #pragma unroll 4
    for (int k = 0; k < NC; k++){
      float a[5];
      #pragma unroll
      for (int i = 0; i < 5; i++) a[i] = sy[(warp*5+i)*NC + k];
      float w[4];
      #pragma unroll
      for (int j = 0; j < 4; j++) w[j] = P.ch2w[k*NC + lane + 32*j];
      #pragma unroll
      for (int i = 0; i < 5; i++)
        #pragma unroll
        for (int j = 0; j < 4; j++) acc[i][j] += a[i]*w[j];
    }
    #pragma unroll
    for (int i = 0; i < 5; i++){
      int v = warp*5 + i;
      const float* tlrow = P.tl_table   + sidx[v]    * NC;
      const float* ltrow = P.lane_table + sidx[NV+v] * NC;
      #pragma unroll
      for (int j = 0; j < 4; j++){
        int c = lane + 32*j;
        sf[v*NC + c] = acc[i][j] + P.ch2b[c] + tlrow[c] + ltrow[c];
      }
    }
  }
  __syncthreads();

  // ---------------- stage 2: token expansion 20 -> 64 -------------------
  {
    stage_w(wb, P.tk1w, tid, (NV*NT)/4);
    __syncthreads();
    float acc[16][4];
    zero_acc(acc);
    gemm_cu<NV>(sf, wb, acc, lane, warp);   // t1[c][u] = sum_v f0[v][c]*w[v][u]
    __syncthreads();
    #pragma unroll
    for (int i = 0; i < 16; i++){
      int u = warp*16 + i;
      float b = P.tk1b[u];
      #pragma unroll
      for (int j = 0; j < 4; j++)
        sy[u*NC + lane + 32*j] = gelu_f(acc[i][j] + b);
    }
    __syncthreads();
    stage_w(wb, P.tk2w, tid, (NT*NT)/4);
    __syncthreads();
    zero_acc(acc);
    gemm_cu<NT>(sy, wb, acc, lane, warp);   // f[t][c] = sum_u t1[u][c... ]*w2[u][t]
    #pragma unroll
    for (int i = 0; i < 16; i++){
      int t = warp*16 + i;
      float b = P.tk2b[t];
      #pragma unroll
      for (int j = 0; j < 4; j++)
        sf[t*NC + lane + 32*j] = acc[i][j] + b;
    }
  }
  __syncthreads();

  // ---------------- mixer blocks ----------------------------------------
  for (int d = 0; d < NDEPTH; d++){
    // LN1 -> sy
    {
      float wg[4], bg[4];
      #pragma unroll
      for (int j = 0; j < 4; j++){
        wg[j] = P.bn1w[d*NC + lane + 32*j];
        bg[j] = P.bn1b[d*NC + lane + 32*j];
      }
      layernorm(sf, sy, wg, bg, lane, warp);
    }
    __syncthreads();

    // token mix: z1[u][c] = gelu(sum_t y[t][c]*W1[t][u] + b1[u])
    stage_w(wb, P.bt1w + d*NT*NT, tid, (NT*NT)/4);
    __syncthreads();
    {
      float acc[16][4];
      zero_acc(acc);
      gemm_cu<NT>(sy, wb, acc, lane, warp);
      __syncthreads();
      #pragma unroll
      for (int i = 0; i < 16; i++){
        int u = warp*16 + i;
        float b = P.bt1b[d*NT + u];
        #pragma unroll
        for (int j = 0; j < 4; j++)
          sy[u*NC + lane + 32*j] = gelu_f(acc[i][j] + b);
      }
      __syncthreads();
      stage_w(wb, P.bt2w + d*NT*NT, tid, (NT*NT)/4);
      __syncthreads();
      zero_acc(acc);
      gemm_cu<NT>(sy, wb, acc, lane, warp);  // z2[t][c]
      #pragma unroll
      for (int i = 0; i < 16; i++){
        int t = warp*16 + i;
        float b = P.bt2b[d*NT + t];
        #pragma unroll
        for (int j = 0; j < 4; j++)
          sf[t*NC + lane + 32*j] += acc[i][j] + b;   // residual
      }
    }
    __syncthreads();

    // LN2 -> sy
    {
      float wg[4], bg[4];
      #pragma unroll
      for (int j = 0; j < 4; j++){
        wg[j] = P.bn2w[d*NC + lane + 32*j];
        bg[j] = P.bn2b[d*NC + lane + 32*j];
      }
      layernorm(sf, sy, wg, bg, lane, warp);
    }
    __syncthreads();

    // channel mix C1: h[t][j] = gelu(sum_c y[t][c]*Wc1[c][j] + b)
    {
      float acc[16][4];
      zero_acc(acc);
      for (int kt = 0; kt < 4; kt++){
        stage_w(wb, P.bc1w + d*NC*NC + kt*32*NC, tid, (32*NC)/4);
        __syncthreads();
        gemm_tj_tile(sy, wb, acc, lane, warp, kt*32);
        __syncthreads();
      }
      #pragma unroll
      for (int i = 0; i < 16; i++){
        int t = warp*16 + i;
        #pragma unroll
        for (int j = 0; j < 4; j++){
          int jj = lane + 32*j;
          sy[t*NC + jj] = gelu_f(acc[i][j] + P.bc1b[d*NC + jj]);
        }
      }
      __syncthreads();
      // channel mix C2: f[t][c] += sum_j h[t][j]*Wc2[j][c] + b2[c]
      zero_acc(acc);
      for (int kt = 0; kt < 4; kt++){
        stage_w(wb, P.bc2w + d*NC*NC + kt*32*NC, tid, (32*NC)/4);
        __syncthreads();
        gemm_tj_tile(sy, wb, acc, lane, warp, kt*32);
        __syncthreads();
      }
      #pragma unroll
      for (int i = 0; i < 16; i++){
        int t = warp*16 + i;
        #pragma unroll
        for (int j = 0; j < 4; j++){
          int c = lane + 32*j;
          sf[t*NC + c] += acc[i][j] + P.bc2b[d*NC + c];
        }
      }
    }
    __syncthreads();
  }

  // ---------------- epilogue: mean over tokens, LN, emb MLP -------------
  float fm = 0.f;
  for (int t = 0; t < NT; t++) fm += sf[t*NC + tid];
  fm *= (1.f/NT);
  {
    float s = fm, q = fm*fm;
    #pragma unroll
    for (int o = 16; o > 0; o >>= 1){
      s += __shfl_xor_sync(0xffffffffu, s, o);
      q += __shfl_xor_sync(0xffffffffu, q, o);
    }
    if (lane == 0){ sred[warp] = s; sred[4+warp] = q; }
  }
  __syncthreads();
  {
    float s = sred[0]+sred[1]+sred[2]+sred[3];
    float q = sred[4]+sred[5]+sred[6]+sred[7];
    float m  = s * (1.f/NC);
    float var = q * (1.f/NC) - m*m;
    float rs = rsqrtf(var + 1e-5f);
    float yv = (fm - m)*rs*P.nw[tid] + P.nb[tid];
    sy[tid] = yv;
  }
  __syncthreads();
  // emb fc1 (128 -> 192)
  {
    float a0 = P.e1b[tid];
    float a1 = (tid < 64) ? P.e1b[128 + tid] : 0.f;
    #pragma unroll 4
    for (int c = 0; c < NC; c++){
      float av = sy[c];
      a0 += av * P.e1w[c*NH + tid];
      if (tid < 64) a1 += av * P.e1w[c*NH + 128 + tid];
    }
    sy[NC + tid] = gelu_f(a0);
    if (tid < 64) sy[NC + 128 + tid] = gelu_f(a1);
  }
  __syncthreads();
  // emb fc2 (192 -> 192), apply valid, write out
  {
    float o0 = P.e2b[tid];
    float o1 = (tid < 64) ? P.e2b[128 + tid] : 0.f;
    #pragma unroll 4
    for (int j = 0; j < NH; j++){
      float hv = sy[NC + j];
      o0 += hv * P.e2w[j*NH + tid];
      if (tid < 64) o1 += hv * P.e2w[j*NH + 128 + tid];
    }
    float valid = sidx[3*NV] ? 0.f : 1.f;
    float* outr = P.out + (size_t)r * NH;
    outr[tid] = o0 * valid;
    if (tid < 64) outr[128 + tid] = o1 * valid;
  }
}

extern "C" void kernel_launch(void* const* d_in, const int* in_sizes, int n_in,
                              void* d_out, int out_size){
  (void)in_sizes; (void)n_in; (void)out_size;
  Params P;
  P.x         = (const float*)d_in[0];
  P.tl_table  = (const float*)d_in[1];
  P.lane_table= (const float*)d_in[2];
  P.ch1w = (const float*)d_in[3];  P.ch1b = (const float*)d_in[4];
  P.ch2w = (const float*)d_in[5];  P.ch2b = (const float*)d_in[6];
  P.tk1w = (const float*)d_in[7];  P.tk1b = (const float*)d_in[8];
  P.tk2w = (const float*)d_in[9];  P.tk2b = (const float*)d_in[10];
  P.bn1w = (const float*)d_in[11]; P.bn1b = (const float*)d_in[12];
  P.bt1w = (const float*)d_in[13]; P.bt1b = (const float*)d_in[14];
  P.bt2w = (const float*)d_in[15]; P.bt2b = (const float*)d_in[16];
  P.bn2w = (const float*)d_in[17]; P.bn2b = (const float*)d_in[18];
  P.bc1w = (const float*)d_in[19]; P.bc1b = (const float*)d_in[20];
  P.bc2w = (const float*)d_in[21]; P.bc2b = (const float*)d_in[22];
  P.nw   = (const float*)d_in[23]; P.nb   = (const float*)d_in[24];
  P.e1w  = (const float*)d_in[25]; P.e1b  = (const float*)d_in[26];
  P.e2w  = (const float*)d_in[27]; P.e2b  = (const float*)d_in[28];

  float* ob = (float*)d_out;
  P.out      = ob;                               // [8192, 192]
  P.mask_out = ob + (size_t)NR*NH;               // [8192]  (0/1 as float)
  P.pos_out  = ob + (size_t)NR*NH + NR;          // [8192, 5]

  cudaFuncSetAttribute(lane_fusion_kernel,
                       cudaFuncAttributeMaxDynamicSharedMemorySize, SMEM_BYTES);
  lane_fusion_kernel<<<NR, 128, SMEM_BYTES>>>(P);
}

// round 2
// speedup vs baseline: 1.2626x; 1.2626x over previous
#include <cuda_runtime.h>
#include <math.h>

#define NV 20
#define NC 128
#define NT 64
#define NH 192
#define N_TL 9
#define N_LT 20
#define NDEPTH 3

#define AP20 22
#define AP64 66
#define WPC  34

// shared memory layout (floats)
#define OFF_SF   0        // 8192 : state f[64][128]; fT[128][22] overlays base early
#define OFF_SY   8192     // 8448 : yT/zT[128][66] or natural [64][128] or h1[24][128]
#define OFF_W0   16640    // 4352
#define OFF_W1   20992    // 4352
#define OFF_SG   25344    // 96
#define OFF_SRED 25440    // 16
#define OFF_SIDX 25456    // 64 ints
#define SMEM_FLOATS 25520
#define SMEM_BYTES (SMEM_FLOATS*4)

typedef unsigned long long u64;
union F2U { float2 f2; u64 u; float f[2]; };

struct Params {
  const float* x;
  const float* tl_table; const float* lane_table;
  const float* ch1w; const float* ch1b; const float* ch2w; const float* ch2b;
  const float* tk1w; const float* tk1b; const float* tk2w; const float* tk2b;
  const float* bn1w; const float* bn1b;
  const float* bt1w; const float* bt1b; const float* bt2w; const float* bt2b;
  const float* bn2w; const float* bn2b;
  const float* bc1w; const float* bc1b; const float* bc2w; const float* bc2b;
  const float* nw;  const float* nb;
  const float* e1w; const float* e1b; const float* e2w; const float* e2b;
  float* out; float* mask_out; float* pos_out;
};

__device__ __forceinline__ float gelu_f(float v){
  return 0.5f * v * (1.0f + erff(v * 0.70710678118654752440f));
}

__device__ __forceinline__ u64 lds_f2(const float* p){
  F2U t; t.f2 = *reinterpret_cast<const float2*>(p); return t.u;
}
__device__ __forceinline__ void ffma2(u64& d, u64 a, u64 b){
  asm("fma.rn.f32x2 %0, %1, %2, %0;" : "+l"(d) : "l"(a), "l"(b));
}
__device__ __forceinline__ float f2sum(u64 v){ F2U t; t.u = v; return t.f[0] + t.f[1]; }

// ---- token-type GEMM: out[u][c] = sum_k aT[c][k] * wT[u][k], k packed in pairs
template<int K2, int AP, int WP>
__device__ __forceinline__ void tok_gemm(const float* __restrict__ aT,
                                         const float* __restrict__ wT,
                                         u64 acc[8][4], int lane, int warp){
  #pragma unroll 4
  for (int k2 = 0; k2 < K2; k2++){
    const int k = 2*k2;
    u64 a[4], w[8];
    #pragma unroll
    for (int j = 0; j < 4; j++) a[j] = lds_f2(aT + (lane + 32*j)*AP + k);
    #pragma unroll
    for (int p = 0; p < 8; p++) w[p] = lds_f2(wT + (warp*8 + p)*WP + k);
    #pragma unroll
    for (int p = 0; p < 8; p++)
      #pragma unroll
      for (int j = 0; j < 4; j++) ffma2(acc[p][j], w[p], a[j]);
  }
}

// ---- channel-type GEMM tile (32 k's): A natural [row][128], wbT [c][34]
template<int I>
__device__ __forceinline__ void chan_tile(const float* __restrict__ A,
                                          const float* __restrict__ wbT,
                                          u64 acc[I][4], int lane, int warp, int k0){
  #pragma unroll 4
  for (int k2 = 0; k2 < 16; k2++){
    u64 a[I], w[4];
    #pragma unroll
    for (int j = 0; j < 4; j++) w[j] = lds_f2(wbT + (lane + 32*j)*WPC + 2*k2);
    #pragma unroll
    for (int i = 0; i < I; i++) a[i] = lds_f2(A + (warp*I + i)*NC + k0 + 2*k2);
    #pragma unroll
    for (int i = 0; i < I; i++)
      #pragma unroll
      for (int j = 0; j < 4; j++) ffma2(acc[i][j], a[i], w[j]);
  }
}

__device__ __forceinline__ void ldg_tile(float4 r[4], const float* __restrict__ gk0, int tid){
  const float4* g4 = reinterpret_cast<const float4*>(gk0);
  #pragma unroll
  for (int q = 0; q < 4; q++) r[q] = g4[tid + 256*q];
}
__device__ __forceinline__ void sts_tile(const float4 r[4], float* wbT, int tid){
  #pragma unroll
  for (int q = 0; q < 4; q++){
    int idx = tid + 256*q;
    int kk  = idx >> 5;     // 0..31
    int c4  = idx & 31;     // 0..31 (c = 4*c4..)
    wbT[(c4*4+0)*WPC + kk] = r[q].x;
    wbT[(c4*4+1)*WPC + kk] = r[q].y;
    wbT[(c4*4+2)*WPC + kk] = r[q].z;
    wbT[(c4*4+3)*WPC + kk] = r[q].w;
  }
}

// full K=128 channel GEMM with ping-pong staged transposed weight tiles
template<int I>
__device__ void chan_gemm_full(const float* __restrict__ A, const float* __restrict__ gw,
                               u64 acc[I][4], float* wb0, float* wb1,
                               int tid, int lane, int warp){
  float4 pre[4];
  ldg_tile(pre, gw, tid);
  sts_tile(pre, wb0, tid);
  __syncthreads();
  #pragma unroll
  for (int t = 0; t < 4; t++){
    if (t < 3) ldg_tile(pre, gw + (t+1)*32*NC, tid);
    chan_tile<I>(A, (t & 1) ? wb1 : wb0, acc, lane, warp, t*32);
    if (t < 3) sts_tile(pre, ((t+1) & 1) ? wb1 : wb0, tid);
    __syncthreads();
  }
}

// transpose-stage a token-type weight [K][64] -> wT[64][pad]
__device__ __forceinline__ void stage_tokW(float* wT, const float* __restrict__ g,
                                           int K, int pad, int tid){
  for (int idx = tid; idx < K*64; idx += 256){
    int u = idx & 63, v = idx >> 6;
    wT[u*pad + v] = g[idx];     // g[v*64+u] == g[idx]
  }
}

template<int IJ>
__device__ __forceinline__ void zero_acc8(u64 acc[IJ][4]){
  #pragma unroll
  for (int i = 0; i < IJ; i++)
    #pragma unroll
    for (int j = 0; j < 4; j++) acc[i][j] = 0ull;
}

__global__ void __launch_bounds__(256, 2)
lane_fusion_kernel(Params P){
  extern __shared__ float smem[];
  float* sf  = smem + OFF_SF;
  float* fT  = smem + OFF_SF;      // overlay, dead before sf first written
  float* sy  = smem + OFF_SY;
  float* wb0 = smem + OFF_W0;
  float* wb1 = smem + OFF_W1;
  float* sg  = smem + OFF_SG;
  float* sred= smem + OFF_SRED;
  int*   sidx= (int*)(smem + OFF_SIDX);

  const int tid  = threadIdx.x;
  const int lane = tid & 31;
  const int warp = tid >> 5;
  const int r    = blockIdx.x;
  const float* xr = P.x + (size_t)r * (NV*5);

  // ----- preprocess -----
  if (tid < NV){
    float x0 = xr[tid*5+0], x1 = xr[tid*5+1], hg = xr[tid*5+2];
    float x3 = xr[tid*5+3], x4 = xr[tid*5+4];
    float ch = cosf(hg), sh = sinf(hg);
    sg[tid*4+0] = x0; sg[tid*4+1] = x1; sg[tid*4+2] = ch; sg[tid*4+3] = sh;
    int tl = (int)x3; tl = tl < 0 ? 0 : (tl > N_TL-1 ? N_TL-1 : tl);
    int lt = (int)x4; lt = lt < 0 ? 0 : (lt > N_LT-1 ? N_LT-1 : lt);
    sidx[tid]      = tl;
    sidx[NV+tid]   = lt;
    sidx[2*NV+tid] = (x0==0.f && x1==0.f && ch==0.f && sh==0.f) ? 1 : 0;
  }
  if (tid < 5){
    float mid = xr[(NV/2)*5 + tid];
    float sc = (tid==3) ? (1.f/(N_TL-1)) : ((tid==4) ? (1.f/(N_LT-1)) : 1.f);
    P.pos_out[(size_t)r*5 + tid] = mid * sc;
  }
  __syncthreads();
  if (tid == 0){
    int mp = 1;
    for (int v = 0; v < NV; v++) mp &= sidx[2*NV+v];
    sidx[3*NV] = mp;
    P.mask_out[r] = mp ? 1.f : 0.f;
  }

  // ----- stage 1a: h1[v][c] = gelu(g @ ch1w + b) -> sy rows 0..19 (rows 20..23 zero)
  {
    int c  = tid & 127;
    int hf = tid >> 7;
    float w0 = P.ch1w[0*NC + c], w1 = P.ch1w[1*NC + c];
    float w2 = P.ch1w[2*NC + c], w3 = P.ch1w[3*NC + c];
    float b  = P.ch1b[c];
    #pragma unroll
    for (int v = hf*10; v < hf*10 + 10; v++){
      float a = b + sg[v*4+0]*w0 + sg[v*4+1]*w1 + sg[v*4+2]*w2 + sg[v*4+3]*w3;
      sy[v*NC + c] = gelu_f(a);
    }
    if (hf == 0){
      #pragma unroll
      for (int v = NV; v < 24; v++) sy[v*NC + c] = 0.f;
    }
  }
  __syncthreads();

  // ----- stage 1b: f0 = h1 @ ch2w + b + tables  -> fT[c][v] (pad 22)
  {
    u64 acc[3][4]; zero_acc8<3>(acc);
    chan_gemm_full<3>(sy, P.ch2w, acc, wb0, wb1, tid, lane, warp);
    #pragma unroll
    for (int i = 0; i < 3; i++){
      int v = warp*3 + i;
      if (v < NV){
        const float* tlrow = P.tl_table   + sidx[v]    * NC;
        const float* ltrow = P.lane_table + sidx[NV+v] * NC;
        #pragma unroll
        for (int j = 0; j < 4; j++){
          int c = lane + 32*j;
          fT[c*AP20 + v] = f2sum(acc[i][j]) + P.ch2b[c] + tlrow[c] + ltrow[c];
        }
      }
    }
  }
  __syncthreads();

  // ----- token expansion: 20 -> 64 -----
  stage_tokW(wb0, P.tk1w, NV, AP20, tid);
  stage_tokW(wb1, P.tk2w, NT, AP64, tid);
  __syncthreads();
  {
    u64 acc[8][4]; zero_acc8<8>(acc);
    tok_gemm<10, AP20, AP20>(fT, wb0, acc, lane, warp);
    __syncthreads();                       // all done reading fT (sf base) + h1
    #pragma unroll
    for (int p = 0; p < 8; p++){
      int u = warp*8 + p;
      float b = P.tk1b[u];
      #pragma unroll
      for (int j = 0; j < 4; j++)
        sy[(lane+32*j)*AP64 + u] = gelu_f(f2sum(acc[p][j]) + b);   // zT
    }
    __syncthreads();
    zero_acc8<8>(acc);
    tok_gemm<32, AP64, AP64>(sy, wb1, acc, lane, warp);
    #pragma unroll
    for (int p = 0; p < 8; p++){
      int t = warp*8 + p;
      float b = P.tk2b[t];
      #pragma unroll
      for (int j = 0; j < 4; j++)
        sf[t*NC + lane + 32*j] = f2sum(acc[p][j]) + b;
    }
  }
  __syncthreads();

  // ----- mixer blocks -----
  for (int d = 0; d < NDEPTH; d++){
    // LN1 -> yT (sy) ; stage token weights
    {
      float wg[4], bg[4];
      #pragma unroll
      for (int j = 0; j < 4; j++){
        wg[j] = P.bn1w[d*NC + lane + 32*j];
        bg[j] = P.bn1b[d*NC + lane + 32*j];
      }
      for (int t = warp; t < NT; t += 8){
        float v[4]; float s = 0.f, q = 0.f;
        #pragma unroll
        for (int j = 0; j < 4; j++){
          v[j] = sf[t*NC + lane + 32*j];
          s += v[j]; q += v[j]*v[j];
        }
        #pragma unroll
        for (int o = 16; o > 0; o >>= 1){
          s += __shfl_xor_sync(0xffffffffu, s, o);
          q += __shfl_xor_sync(0xffffffffu, q, o);
        }
        float m  = s * (1.f/NC);
        float var = q * (1.f/NC) - m*m;
        float rs = rsqrtf(var + 1e-5f);
        #pragma unroll
        for (int j = 0; j < 4; j++)
          sy[(lane+32*j)*AP64 + t] = (v[j]-m)*rs*wg[j] + bg[j];
      }
    }
    stage_tokW(wb0, P.bt1w + d*NT*NT, NT, AP64, tid);
    stage_tokW(wb1, P.bt2w + d*NT*NT, NT, AP64, tid);
    __syncthreads();

    // token mix
    {
      u64 acc[8][4]; zero_acc8<8>(acc);
      tok_gemm<32, AP64, AP64>(sy, wb0, acc, lane, warp);
      __syncthreads();                     // all reads of yT done before zT overwrite
      #pragma unroll
      for (int p = 0; p < 8; p++){
        int u = warp*8 + p;
        float b = P.bt1b[d*NT + u];
        #pragma unroll
        for (int j = 0; j < 4; j++)
          sy[(lane+32*j)*AP64 + u] = gelu_f(f2sum(acc[p][j]) + b);  // zT
      }
      __syncthreads();
      zero_acc8<8>(acc);
      tok_gemm<32, AP64, AP64>(sy, wb1, acc, lane, warp);
      #pragma unroll
      for (int p = 0; p < 8; p++){
        int t = warp*8 + p;
        float b = P.bt2b[d*NT + t];
        #pragma unroll
        for (int j = 0; j < 4; j++)
          sf[t*NC + lane + 32*j] += f2sum(acc[p][j]) + b;           // residual
      }
    }
    __syncthreads();

    // LN2 -> sy natural [t][c]
    {
      float wg[4], bg[4];
      #pragma unroll
      for (int j = 0; j < 4; j++){
        wg[j] = P.bn2w[d*NC + lane + 32*j];
        bg[j] = P.bn2b[d*NC + lane + 32*j];
      }
      for (int t = warp; t < NT; t += 8){
        float v[4]; float s = 0.f, q = 0.f;
        #pragma unroll
        for (int j = 0; j < 4; j++){
          v[j] = sf[t*NC + lane + 32*j];
          s += v[j]; q += v[j]*v[j];
        }
        #pragma unroll
        for (int o = 16; o > 0; o >>= 1){
          s += __shfl_xor_sync(0xffffffffu, s, o);
          q += __shfl_xor_sync(0xffffffffu, q, o);
        }
        float m  = s * (1.f/NC);
        float var = q * (1.f/NC) - m*m;
        float rs = rsqrtf(var + 1e-5f);
        #pragma unroll
        for (int j = 0; j < 4; j++)
          sy[t*NC + lane + 32*j] = (v[j]-m)*rs*wg[j] + bg[j];
      }
    }
    __syncthreads();

    // channel mix C1: h = gelu(y2 @ Wc1 + b1) -> sy (overwrite after full acc)
    {
      u64 acc[8][4]; zero_acc8<8>(acc);
      chan_gemm_full<8>(sy, P.bc1w + d*NC*NC, acc, wb0, wb1, tid, lane, warp);
      #pragma unroll
      for (int p = 0; p < 8; p++){
        int t = warp*8 + p;
        #pragma unroll
        for (int j = 0; j < 4; j++){
          int jj = lane + 32*j;
          sy[t*NC + jj] = gelu_f(f2sum(acc[p][j]) + P.bc1b[d*NC + jj]);
        }
      }
      __syncthreads();
      // channel mix C2: f += h @ Wc2 + b2
      zero_acc8<8>(acc);
      chan_gemm_full<8>(sy, P.bc2w + d*NC*NC, acc, wb0, wb1, tid, lane, warp);
      #pragma unroll
      for (int p = 0; p < 8; p++){
        int t = warp*8 + p;
        #pragma unroll
        for (int j = 0; j < 4; j++){
          int c = lane + 32*j;
          sf[t*NC + c] += f2sum(acc[p][j]) + P.bc2b[d*NC + c];
        }
      }
    }
    __syncthreads();
  }

  // ----- epilogue: token mean, LN, emb MLP -----
  {
    int c  = tid & 127;
    int hf = tid >> 7;
    float ps = 0.f;
    #pragma unroll 8
    for (int t = hf*32; t < hf*32 + 32; t++) ps += sf[t*NC + c];
    sy[hf*128 + c] = ps;
  }
  __syncthreads();
  float fm = 0.f;
  if (tid < NC){
    fm = (sy[tid] + sy[128 + tid]) * (1.f/NT);
    float s = fm, q = fm*fm;
    #pragma unroll
    for (int o = 16; o > 0; o >>= 1){
      s += __shfl_xor_sync(0xffffffffu, s, o);
      q += __shfl_xor_sync(0xffffffffu, q, o);
    }
    if (lane == 0){ sred[warp] = s; sred[4+warp] = q; }
  }
  __syncthreads();
  if (tid < NC){
    float s = sred[0]+sred[1]+sred[2]+sred[3];
    float q = sred[4]+sred[5]+sred[6]+sred[7];
    float m  = s * (1.f/NC);
    float var = q * (1.f/NC) - m*m;
    float rs = rsqrtf(var + 1e-5f);
    sy[256 + tid] = (fm - m)*rs*P.nw[tid] + P.nb[tid];
  }
  __syncthreads();
  if (tid < NH){
    float a = P.e1b[tid];
    #pragma unroll 8
    for (int c = 0; c < NC; c++) a += sy[256 + c] * P.e1w[c*NH + tid];
    sy[512 + tid] = gelu_f(a);
  }
  __syncthreads();
  if (tid < NH){
    float o = P.e2b[tid];
    #pragma unroll 8
    for (int j = 0; j < NH; j++) o += sy[512 + j] * P.e2w[j*NH + tid];
    float valid = sidx[3*NV] ? 0.f : 1.f;
    P.out[(size_t)r * NH + tid] = o * valid;
  }
}

extern "C" void kernel_launch(void* const* d_in, const int* in_sizes, int n_in,
                              void* d_out, int out_size){
  (void)in_sizes; (void)n_in; (void)out_size;
  Params P;
  P.x         = (const float*)d_in[0];
  P.tl_table  = (const float*)d_in[1];
  P.lane_table= (const float*)d_in[2];
  P.ch1w = (const float*)d_in[3];  P.ch1b = (const float*)d_in[4];
  P.ch2w = (const float*)d_in[5];  P.ch2b = (const float*)d_in[6];
  P.tk1w = (const float*)d_in[7];  P.tk1b = (const float*)d_in[8];
  P.tk2w = (const float*)d_in[9];  P.tk2b = (const float*)d_in[10];
  P.bn1w = (const float*)d_in[11]; P.bn1b = (const float*)d_in[12];
  P.bt1w = (const float*)d_in[13]; P.bt1b = (const float*)d_in[14];
  P.bt2w = (const float*)d_in[15]; P.bt2b = (const float*)d_in[16];
  P.bn2w = (const float*)d_in[17]; P.bn2b = (const float*)d_in[18];
  P.bc1w = (const float*)d_in[19]; P.bc1b = (const float*)d_in[20];
  P.bc2w = (const float*)d_in[21]; P.bc2b = (const float*)d_in[22];
  P.nw   = (const float*)d_in[23]; P.nb   = (const float*)d_in[24];
  P.e1w  = (const float*)d_in[25]; P.e1b  = (const float*)d_in[26];
  P.e2w  = (const float*)d_in[27]; P.e2b  = (const float*)d_in[28];

  const int NRows = 8192;
  float* ob = (float*)d_out;
  P.out      = ob;
  P.mask_out = ob + (size_t)NRows*NH;
  P.pos_out  = ob + (size_t)NRows*NH + NRows;

  cudaFuncSetAttribute(lane_fusion_kernel,
                       cudaFuncAttributeMaxDynamicSharedMemorySize, SMEM_BYTES);
  lane_fusion_kernel<<<NRows, 256, SMEM_BYTES>>>(P);
}

// round 3
// speedup vs baseline: 1.2643x; 1.0013x over previous
#include <cuda_runtime.h>
#include <math.h>

#define NV 20
#define NC 128
#define NT 64
#define NH 192
#define N_TL 9
#define N_LT 20
#define NDEPTH 3

#define AP20 22
#define AP64 66
#define WPC  34

// shared memory layout (floats)
#define OFF_SF   0        // 8192 : state f[64][128]; fT[128][22] overlays base early
#define OFF_SY   8192     // 8448 : yT/zT[128][66] or natural [64][128] or h1[24][128]
#define OFF_W0   16640    // 4352
#define OFF_W1   20992    // 4352
#define OFF_SG   25344    // 96
#define OFF_SRED 25440    // 16
#define OFF_SIDX 25456    // 64 ints
#define SMEM_FLOATS 25520
#define SMEM_BYTES (SMEM_FLOATS*4)

typedef unsigned long long u64;
union F2U { float2 f2; u64 u; float f[2]; };

struct Params {
  const float* x;
  const float* tl_table; const float* lane_table;
  const float* ch1w; const float* ch1b; const float* ch2w; const float* ch2b;
  const float* tk1w; const float* tk1b; const float* tk2w; const float* tk2b;
  const float* bn1w; const float* bn1b;
  const float* bt1w; const float* bt1b; const float* bt2w; const float* bt2b;
  const float* bn2w; const float* bn2b;
  const float* bc1w; const float* bc1b; const float* bc2w; const float* bc2b;
  const float* nw;  const float* nb;
  const float* e1w; const float* e1b; const float* e2w; const float* e2b;
  float* out; float* mask_out; float* pos_out;
};

__device__ __forceinline__ float gelu_f(float v){
  return 0.5f * v * (1.0f + erff(v * 0.70710678118654752440f));
}

__device__ __forceinline__ u64 lds_f2(const float* p){
  F2U t; t.f2 = *reinterpret_cast<const float2*>(p); return t.u;
}
__device__ __forceinline__ void ffma2(u64& d, u64 a, u64 b){
  asm("fma.rn.f32x2 %0, %1, %2, %0;" : "+l"(d) : "l"(a), "l"(b));
}
__device__ __forceinline__ float f2sum(u64 v){ F2U t; t.u = v; return t.f[0] + t.f[1]; }

// ---- token-type GEMM: out[u][c] = sum_k aT[c][k] * wT[u][k], k packed in pairs
template<int K2, int AP, int WP>
__device__ __forceinline__ void tok_gemm(const float* __restrict__ aT,
                                         const float* __restrict__ wT,
                                         u64 acc[8][4], int lane, int warp){
  #pragma unroll 4
  for (int k2 = 0; k2 < K2; k2++){
    const int k = 2*k2;
    u64 a[4], w[8];
    #pragma unroll
    for (int j = 0; j < 4; j++) a[j] = lds_f2(aT + (lane + 32*j)*AP + k);
    #pragma unroll
    for (int p = 0; p < 8; p++) w[p] = lds_f2(wT + (warp*8 + p)*WP + k);
    #pragma unroll
    for (int p = 0; p < 8; p++)
      #pragma unroll
      for (int j = 0; j < 4; j++) ffma2(acc[p][j], w[p], a[j]);
  }
}

// ---- channel-type GEMM tile (32 k's): A natural [row][128], wbT [c][34]
template<int I>
__device__ __forceinline__ void chan_tile(const float* __restrict__ A,
                                          const float* __restrict__ wbT,
                                          u64 acc[I][4], int lane, int warp, int k0){
  #pragma unroll 4
  for (int k2 = 0; k2 < 16; k2++){
    u64 a[I], w[4];
    #pragma unroll
    for (int j = 0; j < 4; j++) w[j] = lds_f2(wbT + (lane + 32*j)*WPC + 2*k2);
    #pragma unroll
    for (int i = 0; i < I; i++) a[i] = lds_f2(A + (warp*I + i)*NC + k0 + 2*k2);
    #pragma unroll
    for (int i = 0; i < I; i++)
      #pragma unroll
      for (int j = 0; j < 4; j++) ffma2(acc[i][j], a[i], w[j]);
  }
}

__device__ __forceinline__ void ldg_tile(float4 r[4], const float* __restrict__ gk0, int tid){
  const float4* g4 = reinterpret_cast<const float4*>(gk0);
  #pragma unroll
  for (int q = 0; q < 4; q++) r[q] = g4[tid + 256*q];
}
__device__ __forceinline__ void sts_tile(const float4 r[4], float* wbT, int tid){
  #pragma unroll
  for (int q = 0; q < 4; q++){
    int idx = tid + 256*q;
    int kk  = idx >> 5;     // 0..31
    int c4  = idx & 31;     // 0..31 (c = 4*c4..)
    wbT[(c4*4+0)*WPC + kk] = r[q].x;
    wbT[(c4*4+1)*WPC + kk] = r[q].y;
    wbT[(c4*4+2)*WPC + kk] = r[q].z;
    wbT[(c4*4+3)*WPC + kk] = r[q].w;
  }
}

// full K=128 channel GEMM with ping-pong staged transposed weight tiles
template<int I>
__device__ void chan_gemm_full(const float* __restrict__ A, const float* __restrict__ gw,
                               u64 acc[I][4], float* wb0, float* wb1,
                               int tid, int lane, int warp){
  float4 pre[4];
  ldg_tile(pre, gw, tid);
  sts_tile(pre, wb0, tid);
  __syncthreads();
  #pragma unroll
  for (int t = 0; t < 4; t++){
    if (t < 3) ldg_tile(pre, gw + (t+1)*32*NC, tid);
    chan_tile<I>(A, (t & 1) ? wb1 : wb0, acc, lane, warp, t*32);
    if (t < 3) sts_tile(pre, ((t+1) & 1) ? wb1 : wb0, tid);
    __syncthreads();
  }
}

// transpose-stage a token-type weight [K][64] -> wT[64][pad]
__device__ __forceinline__ void stage_tokW(float* wT, const float* __restrict__ g,
                                           int K, int pad, int tid){
  for (int idx = tid; idx < K*64; idx += 256){
    int u = idx & 63, v = idx >> 6;
    wT[u*pad + v] = g[idx];     // g[v*64+u] == g[idx]
  }
}

template<int IJ>
__device__ __forceinline__ void zero_acc8(u64 acc[IJ][4]){
  #pragma unroll
  for (int i = 0; i < IJ; i++)
    #pragma unroll
    for (int j = 0; j < 4; j++) acc[i][j] = 0ull;
}

__global__ void __launch_bounds__(256, 2)
lane_fusion_kernel(Params P){
  extern __shared__ float smem[];
  float* sf  = smem + OFF_SF;
  float* fT  = smem + OFF_SF;      // overlay, dead before sf first written
  float* sy  = smem + OFF_SY;
  float* wb0 = smem + OFF_W0;
  float* wb1 = smem + OFF_W1;
  float* sg  = smem + OFF_SG;
  float* sred= smem + OFF_SRED;
  int*   sidx= (int*)(smem + OFF_SIDX);

  const int tid  = threadIdx.x;
  const int lane = tid & 31;
  const int warp = tid >> 5;
  const int r    = blockIdx.x;
  const float* xr = P.x + (size_t)r * (NV*5);

  // ----- preprocess -----
  if (tid < NV){
    float x0 = xr[tid*5+0], x1 = xr[tid*5+1], hg = xr[tid*5+2];
    float x3 = xr[tid*5+3], x4 = xr[tid*5+4];
    float ch = cosf(hg), sh = sinf(hg);
    sg[tid*4+0] = x0; sg[tid*4+1] = x1; sg[tid*4+2] = ch; sg[tid*4+3] = sh;
    int tl = (int)x3; tl = tl < 0 ? 0 : (tl > N_TL-1 ? N_TL-1 : tl);
    int lt = (int)x4; lt = lt < 0 ? 0 : (lt > N_LT-1 ? N_LT-1 : lt);
    sidx[tid]      = tl;
    sidx[NV+tid]   = lt;
    sidx[2*NV+tid] = (x0==0.f && x1==0.f && ch==0.f && sh==0.f) ? 1 : 0;
  }
  if (tid < 5){
    float mid = xr[(NV/2)*5 + tid];
    float sc = (tid==3) ? (1.f/(N_TL-1)) : ((tid==4) ? (1.f/(N_LT-1)) : 1.f);
    P.pos_out[(size_t)r*5 + tid] = mid * sc;
  }
  __syncthreads();
  if (tid == 0){
    int mp = 1;
    for (int v = 0; v < NV; v++) mp &= sidx[2*NV+v];
    sidx[3*NV] = mp;
    P.mask_out[r] = mp ? 1.f : 0.f;
  }

  // ----- stage 1a: h1[v][c] = gelu(g @ ch1w + b) -> sy rows 0..19 (rows 20..23 zero)
  {
    int c  = tid & 127;
    int hf = tid >> 7;
    float w0 = P.ch1w[0*NC + c], w1 = P.ch1w[1*NC + c];
    float w2 = P.ch1w[2*NC + c], w3 = P.ch1w[3*NC + c];
    float b  = P.ch1b[c];
    #pragma unroll
    for (int v = hf*10; v < hf*10 + 10; v++){
      float a = b + sg[v*4+0]*w0 + sg[v*4+1]*w1 + sg[v*4+2]*w2 + sg[v*4+3]*w3;
      sy[v*NC + c] = gelu_f(a);
    }
    if (hf == 0){
      #pragma unroll
      for (int v = NV; v < 24; v++) sy[v*NC + c] = 0.f;
    }
  }
  __syncthreads();

  // ----- stage 1b: f0 = h1 @ ch2w + b + tables  -> fT[c][v] (pad 22)
  {
    u64 acc[3][4]; zero_acc8<3>(acc);
    chan_gemm_full<3>(sy, P.ch2w, acc, wb0, wb1, tid, lane, warp);
    #pragma unroll
    for (int i = 0; i < 3; i++){
      int v = warp*3 + i;
      if (v < NV){
        const float* tlrow = P.tl_table   + sidx[v]    * NC;
        const float* ltrow = P.lane_table + sidx[NV+v] * NC;
        #pragma unroll
        for (int j = 0; j < 4; j++){
          int c = lane + 32*j;
          fT[c*AP20 + v] = f2sum(acc[i][j]) + P.ch2b[c] + tlrow[c] + ltrow[c];
        }
      }
    }
  }
  __syncthreads();

  // ----- token expansion: 20 -> 64 -----
  stage_tokW(wb0, P.tk1w, NV, AP20, tid);
  stage_tokW(wb1, P.tk2w, NT, AP64, tid);
  __syncthreads();
  {
    u64 acc[8][4]; zero_acc8<8>(acc);
    tok_gemm<10, AP20, AP20>(fT, wb0, acc, lane, warp);
    __syncthreads();                       // all done reading fT (sf base) + h1
    #pragma unroll
    for (int p = 0; p < 8; p++){
      int u = warp*8 + p;
      float b = P.tk1b[u];
      #pragma unroll
      for (int j = 0; j < 4; j++)
        sy[(lane+32*j)*AP64 + u] = gelu_f(f2sum(acc[p][j]) + b);   // zT
    }
    __syncthreads();
    zero_acc8<8>(acc);
    tok_gemm<32, AP64, AP64>(sy, wb1, acc, lane, warp);
    #pragma unroll
    for (int p = 0; p < 8; p++){
      int t = warp*8 + p;
      float b = P.tk2b[t];
      #pragma unroll
      for (int j = 0; j < 4; j++)
        sf[t*NC + lane + 32*j] = f2sum(acc[p][j]) + b;
    }
  }
  __syncthreads();

  // ----- mixer blocks -----
  for (int d = 0; d < NDEPTH; d++){
    // LN1 -> yT (sy) ; stage token weights
    {
      float wg[4], bg[4];
      #pragma unroll
      for (int j = 0; j < 4; j++){
        wg[j] = P.bn1w[d*NC + lane + 32*j];
        bg[j] = P.bn1b[d*NC + lane + 32*j];
      }
      for (int t = warp; t < NT; t += 8){
        float v[4]; float s = 0.f, q = 0.f;
        #pragma unroll
        for (int j = 0; j < 4; j++){
          v[j] = sf[t*NC + lane + 32*j];
          s += v[j]; q += v[j]*v[j];
        }
        #pragma unroll
        for (int o = 16; o > 0; o >>= 1){
          s += __shfl_xor_sync(0xffffffffu, s, o);
          q += __shfl_xor_sync(0xffffffffu, q, o);
        }
        float m  = s * (1.f/NC);
        float var = q * (1.f/NC) - m*m;
        float rs = rsqrtf(var + 1e-5f);
        #pragma unroll
        for (int j = 0; j < 4; j++)
          sy[(lane+32*j)*AP64 + t] = (v[j]-m)*rs*wg[j] + bg[j];
      }
    }
    stage_tokW(wb0, P.bt1w + d*NT*NT, NT, AP64, tid);
    stage_tokW(wb1, P.bt2w + d*NT*NT, NT, AP64, tid);
    __syncthreads();

    // token mix
    {
      u64 acc[8][4]; zero_acc8<8>(acc);
      tok_gemm<32, AP64, AP64>(sy, wb0, acc, lane, warp);
      __syncthreads();                     // all reads of yT done before zT overwrite
      #pragma unroll
      for (int p = 0; p < 8; p++){
        int u = warp*8 + p;
        float b = P.bt1b[d*NT + u];
        #pragma unroll
        for (int j = 0; j < 4; j++)
          sy[(lane+32*j)*AP64 + u] = gelu_f(f2sum(acc[p][j]) + b);  // zT
      }
      __syncthreads();
      zero_acc8<8>(acc);
      tok_gemm<32, AP64, AP64>(sy, wb1, acc, lane, warp);
      #pragma unroll
      for (int p = 0; p < 8; p++){
        int t = warp*8 + p;
        float b = P.bt2b[d*NT + t];
        #pragma unroll
        for (int j = 0; j < 4; j++)
          sf[t*NC + lane + 32*j] += f2sum(acc[p][j]) + b;           // residual
      }
    }
    __syncthreads();

    // LN2 -> sy natural [t][c]
    {
      float wg[4], bg[4];
      #pragma unroll
      for (int j = 0; j < 4; j++){
        wg[j] = P.bn2w[d*NC + lane + 32*j];
        bg[j] = P.bn2b[d*NC + lane + 32*j];
      }
      for (int t = warp; t < NT; t += 8){
        float v[4]; float s = 0.f, q = 0.f;
        #pragma unroll
        for (int j = 0; j < 4; j++){
          v[j] = sf[t*NC + lane + 32*j];
          s += v[j]; q += v[j]*v[j];
        }
        #pragma unroll
        for (int o = 16; o > 0; o >>= 1){
          s += __shfl_xor_sync(0xffffffffu, s, o);
          q += __shfl_xor_sync(0xffffffffu, q, o);
        }
        float m  = s * (1.f/NC);
        float var = q * (1.f/NC) - m*m;
        float rs = rsqrtf(var + 1e-5f);
        #pragma unroll
        for (int j = 0; j < 4; j++)
          sy[t*NC + lane + 32*j] = (v[j]-m)*rs*wg[j] + bg[j];
      }
    }
    __syncthreads();

    // channel mix C1: h = gelu(y2 @ Wc1 + b1) -> sy (overwrite after full acc)
    {
      u64 acc[8][4]; zero_acc8<8>(acc);
      chan_gemm_full<8>(sy, P.bc1w + d*NC*NC, acc, wb0, wb1, tid, lane, warp);
      #pragma unroll
      for (int p = 0; p < 8; p++){
        int t = warp*8 + p;
        #pragma unroll
        for (int j = 0; j < 4; j++){
          int jj = lane + 32*j;
          sy[t*NC + jj] = gelu_f(f2sum(acc[p][j]) + P.bc1b[d*NC + jj]);
        }
      }
      __syncthreads();
      // channel mix C2: f += h @ Wc2 + b2
      zero_acc8<8>(acc);
      chan_gemm_full<8>(sy, P.bc2w + d*NC*NC, acc, wb0, wb1, tid, lane, warp);
      #pragma unroll
      for (int p = 0; p < 8; p++){
        int t = warp*8 + p;
        #pragma unroll
        for (int j = 0; j < 4; j++){
          int c = lane + 32*j;
          sf[t*NC + c] += f2sum(acc[p][j]) + P.bc2b[d*NC + c];
        }
      }
    }
    __syncthreads();
  }

  // ----- epilogue: token mean, LN, emb MLP -----
  {
    int c  = tid & 127;
    int hf = tid >> 7;
    float ps = 0.f;
    #pragma unroll 8
    for (int t = hf*32; t < hf*32 + 32; t++) ps += sf[t*NC + c];
    sy[hf*128 + c] = ps;
  }
  __syncthreads();
  float fm = 0.f;
  if (tid < NC){
    fm = (sy[tid] + sy[128 + tid]) * (1.f/NT);
    float s = fm, q = fm*fm;
    #pragma unroll
    for (int o = 16; o > 0; o >>= 1){
      s += __shfl_xor_sync(0xffffffffu, s, o);
      q += __shfl_xor_sync(0xffffffffu, q, o);
    }
    if (lane == 0){ sred[warp] = s; sred[4+warp] = q; }
  }
  __syncthreads();
  if (tid < NC){
    float s = sred[0]+sred[1]+sred[2]+sred[3];
    float q = sred[4]+sred[5]+sred[6]+sred[7];
    float m  = s * (1.f/NC);
    float var = q * (1.f/NC) - m*m;
    float rs = rsqrtf(var + 1e-5f);
    sy[256 + tid] = (fm - m)*rs*P.nw[tid] + P.nb[tid];
  }
  __syncthreads();
  if (tid < NH){
    float a = P.e1b[tid];
    #pragma unroll 8
    for (int c = 0; c < NC; c++) a += sy[256 + c] * P.e1w[c*NH + tid];
    sy[512 + tid] = gelu_f(a);
  }
  __syncthreads();
  if (tid < NH){
    float o = P.e2b[tid];
    #pragma unroll 8
    for (int j = 0; j < NH; j++) o += sy[512 + j] * P.e2w[j*NH + tid];
    float valid = sidx[3*NV] ? 0.f : 1.f;
    P.out[(size_t)r * NH + tid] = o * valid;
  }
}

extern "C" void kernel_launch(void* const* d_in, const int* in_sizes, int n_in,
                              void* d_out, int out_size){
  (void)in_sizes; (void)n_in; (void)out_size;
  Params P;
  P.x         = (const float*)d_in[0];
  P.tl_table  = (const float*)d_in[1];
  P.lane_table= (const float*)d_in[2];
  P.ch1w = (const float*)d_in[3];  P.ch1b = (const float*)d_in[4];
  P.ch2w = (const float*)d_in[5];  P.ch2b = (const float*)d_in[6];
  P.tk1w = (const float*)d_in[7];  P.tk1b = (const float*)d_in[8];
  P.tk2w = (const float*)d_in[9];  P.tk2b = (const float*)d_in[10];
  P.bn1w = (const float*)d_in[11]; P.bn1b = (const float*)d_in[12];
  P.bt1w = (const float*)d_in[13]; P.bt1b = (const float*)d_in[14];
  P.bt2w = (const float*)d_in[15]; P.bt2b = (const float*)d_in[16];
  P.bn2w = (const float*)d_in[17]; P.bn2b = (const float*)d_in[18];
  P.bc1w = (const float*)d_in[19]; P.bc1b = (const float*)d_in[20];
  P.bc2w = (const float*)d_in[21]; P.bc2b = (const float*)d_in[22];
  P.nw   = (const float*)d_in[23]; P.nb   = (const float*)d_in[24];
  P.e1w  = (const float*)d_in[25]; P.e1b  = (const float*)d_in[26];
  P.e2w  = (const float*)d_in[27]; P.e2b  = (const float*)d_in[28];

  const int NRows = 8192;
  float* ob = (float*)d_out;
  P.out      = ob;
  P.mask_out = ob + (size_t)NRows*NH;
  P.pos_out  = ob + (size_t)NRows*NH + NRows;

  cudaFuncSetAttribute(lane_fusion_kernel,
                       cudaFuncAttributeMaxDynamicSharedMemorySize, SMEM_BYTES);
  lane_fusion_kernel<<<NRows, 256, SMEM_BYTES>>>(P);
}

// round 4
// speedup vs baseline: 1.2643x; 1.0000x over previous
#include <cuda_runtime.h>
#include <math.h>

#define NV 20
#define NC 128
#define NT 64
#define NH 192
#define N_TL 9
#define N_LT 20
#define NDEPTH 3

#define AP20 22
#define AP64 66
#define WPC  34

// shared memory layout (floats)
#define OFF_SF   0        // 8192 : state f[64][128]; fT[128][22] overlays base early
#define OFF_SY   8192     // 8448 : yT/zT[128][66] or natural [64][128] or h1[24][128]
#define OFF_W0   16640    // 4352
#define OFF_W1   20992    // 4352
#define OFF_SG   25344    // 96
#define OFF_SRED 25440    // 16
#define OFF_SIDX 25456    // 64 ints
#define SMEM_FLOATS 25520
#define SMEM_BYTES (SMEM_FLOATS*4)

typedef unsigned long long u64;
union F2U { float2 f2; u64 u; float f[2]; };

struct Params {
  const float* x;
  const float* tl_table; const float* lane_table;
  const float* ch1w; const float* ch1b; const float* ch2w; const float* ch2b;
  const float* tk1w; const float* tk1b; const float* tk2w; const float* tk2b;
  const float* bn1w; const float* bn1b;
  const float* bt1w; const float* bt1b; const float* bt2w; const float* bt2b;
  const float* bn2w; const float* bn2b;
  const float* bc1w; const float* bc1b; const float* bc2w; const float* bc2b;
  const float* nw;  const float* nb;
  const float* e1w; const float* e1b; const float* e2w; const float* e2b;
  float* out; float* mask_out; float* pos_out;
};

__device__ __forceinline__ float gelu_f(float v){
  return 0.5f * v * (1.0f + erff(v * 0.70710678118654752440f));
}

__device__ __forceinline__ u64 lds_f2(const float* p){
  F2U t; t.f2 = *reinterpret_cast<const float2*>(p); return t.u;
}
__device__ __forceinline__ void ffma2(u64& d, u64 a, u64 b){
  asm("fma.rn.f32x2 %0, %1, %2, %0;" : "+l"(d) : "l"(a), "l"(b));
}
__device__ __forceinline__ float f2sum(u64 v){ F2U t; t.u = v; return t.f[0] + t.f[1]; }

// ---- token-type GEMM: out[u][c] = sum_k aT[c][k] * wT[u][k], k packed in pairs
template<int K2, int AP, int WP>
__device__ __forceinline__ void tok_gemm(const float* __restrict__ aT,
                                         const float* __restrict__ wT,
                                         u64 acc[8][4], int lane, int warp){
  #pragma unroll 4
  for (int k2 = 0; k2 < K2; k2++){
    const int k = 2*k2;
    u64 a[4], w[8];
    #pragma unroll
    for (int j = 0; j < 4; j++) a[j] = lds_f2(aT + (lane + 32*j)*AP + k);
    #pragma unroll
    for (int p = 0; p < 8; p++) w[p] = lds_f2(wT + (warp*8 + p)*WP + k);
    #pragma unroll
    for (int p = 0; p < 8; p++)
      #pragma unroll
      for (int j = 0; j < 4; j++) ffma2(acc[p][j], w[p], a[j]);
  }
}

// ---- channel-type GEMM tile (32 k's): A natural [row][128], wbT [c][34]
template<int I>
__device__ __forceinline__ void chan_tile(const float* __restrict__ A,
                                          const float* __restrict__ wbT,
                                          u64 acc[I][4], int lane, int warp, int k0){
  #pragma unroll 4
  for (int k2 = 0; k2 < 16; k2++){
    u64 a[I], w[4];
    #pragma unroll
    for (int j = 0; j < 4; j++) w[j] = lds_f2(wbT + (lane + 32*j)*WPC + 2*k2);
    #pragma unroll
    for (int i = 0; i < I; i++) a[i] = lds_f2(A + (warp*I + i)*NC + k0 + 2*k2);
    #pragma unroll
    for (int i = 0; i < I; i++)
      #pragma unroll
      for (int j = 0; j < 4; j++) ffma2(acc[i][j], a[i], w[j]);
  }
}

__device__ __forceinline__ void ldg_tile(float4 r[4], const float* __restrict__ gk0, int tid){
  const float4* g4 = reinterpret_cast<const float4*>(gk0);
  #pragma unroll
  for (int q = 0; q < 4; q++) r[q] = g4[tid + 256*q];
}
__device__ __forceinline__ void sts_tile(const float4 r[4], float* wbT, int tid){
  #pragma unroll
  for (int q = 0; q < 4; q++){
    int idx = tid + 256*q;
    int kk  = idx >> 5;     // 0..31
    int c4  = idx & 31;     // 0..31 (c = 4*c4..)
    wbT[(c4*4+0)*WPC + kk] = r[q].x;
    wbT[(c4*4+1)*WPC + kk] = r[q].y;
    wbT[(c4*4+2)*WPC + kk] = r[q].z;
    wbT[(c4*4+3)*WPC + kk] = r[q].w;
  }
}

// full K=128 channel GEMM with ping-pong staged transposed weight tiles
template<int I>
__device__ void chan_gemm_full(const float* __restrict__ A, const float* __restrict__ gw,
                               u64 acc[I][4], float* wb0, float* wb1,
                               int tid, int lane, int warp){
  float4 pre[4];
  ldg_tile(pre, gw, tid);
  sts_tile(pre, wb0, tid);
  __syncthreads();
  #pragma unroll
  for (int t = 0; t < 4; t++){
    if (t < 3) ldg_tile(pre, gw + (t+1)*32*NC, tid);
    chan_tile<I>(A, (t & 1) ? wb1 : wb0, acc, lane, warp, t*32);
    if (t < 3) sts_tile(pre, ((t+1) & 1) ? wb1 : wb0, tid);
    __syncthreads();
  }
}

// transpose-stage a token-type weight [K][64] -> wT[64][pad]
__device__ __forceinline__ void stage_tokW(float* wT, const float* __restrict__ g,
                                           int K, int pad, int tid){
  for (int idx = tid; idx < K*64; idx += 256){
    int u = idx & 63, v = idx >> 6;
    wT[u*pad + v] = g[idx];     // g[v*64+u] == g[idx]
  }
}

template<int IJ>
__device__ __forceinline__ void zero_acc8(u64 acc[IJ][4]){
  #pragma unroll
  for (int i = 0; i < IJ; i++)
    #pragma unroll
    for (int j = 0; j < 4; j++) acc[i][j] = 0ull;
}

__global__ void __launch_bounds__(256, 2)
lane_fusion_kernel(Params P){
  extern __shared__ float smem[];
  float* sf  = smem + OFF_SF;
  float* fT  = smem + OFF_SF;      // overlay, dead before sf first written
  float* sy  = smem + OFF_SY;
  float* wb0 = smem + OFF_W0;
  float* wb1 = smem + OFF_W1;
  float* sg  = smem + OFF_SG;
  float* sred= smem + OFF_SRED;
  int*   sidx= (int*)(smem + OFF_SIDX);

  const int tid  = threadIdx.x;
  const int lane = tid & 31;
  const int warp = tid >> 5;
  const int r    = blockIdx.x;
  const float* xr = P.x + (size_t)r * (NV*5);

  // ----- preprocess -----
  if (tid < NV){
    float x0 = xr[tid*5+0], x1 = xr[tid*5+1], hg = xr[tid*5+2];
    float x3 = xr[tid*5+3], x4 = xr[tid*5+4];
    float ch = cosf(hg), sh = sinf(hg);
    sg[tid*4+0] = x0; sg[tid*4+1] = x1; sg[tid*4+2] = ch; sg[tid*4+3] = sh;
    int tl = (int)x3; tl = tl < 0 ? 0 : (tl > N_TL-1 ? N_TL-1 : tl);
    int lt = (int)x4; lt = lt < 0 ? 0 : (lt > N_LT-1 ? N_LT-1 : lt);
    sidx[tid]      = tl;
    sidx[NV+tid]   = lt;
    sidx[2*NV+tid] = (x0==0.f && x1==0.f && ch==0.f && sh==0.f) ? 1 : 0;
  }
  if (tid < 5){
    float mid = xr[(NV/2)*5 + tid];
    float sc = (tid==3) ? (1.f/(N_TL-1)) : ((tid==4) ? (1.f/(N_LT-1)) : 1.f);
    P.pos_out[(size_t)r*5 + tid] = mid * sc;
  }
  __syncthreads();
  if (tid == 0){
    int mp = 1;
    for (int v = 0; v < NV; v++) mp &= sidx[2*NV+v];
    sidx[3*NV] = mp;
    P.mask_out[r] = mp ? 1.f : 0.f;
  }

  // ----- stage 1a: h1[v][c] = gelu(g @ ch1w + b) -> sy rows 0..19 (rows 20..23 zero)
  {
    int c  = tid & 127;
    int hf = tid >> 7;
    float w0 = P.ch1w[0*NC + c], w1 = P.ch1w[1*NC + c];
    float w2 = P.ch1w[2*NC + c], w3 = P.ch1w[3*NC + c];
    float b  = P.ch1b[c];
    #pragma unroll
    for (int v = hf*10; v < hf*10 + 10; v++){
      float a = b + sg[v*4+0]*w0 + sg[v*4+1]*w1 + sg[v*4+2]*w2 + sg[v*4+3]*w3;
      sy[v*NC + c] = gelu_f(a);
    }
    if (hf == 0){
      #pragma unroll
      for (int v = NV; v < 24; v++) sy[v*NC + c] = 0.f;
    }
  }
  __syncthreads();

  // ----- stage 1b: f0 = h1 @ ch2w + b + tables  -> fT[c][v] (pad 22)
  {
    u64 acc[3][4]; zero_acc8<3>(acc);
    chan_gemm_full<3>(sy, P.ch2w, acc, wb0, wb1, tid, lane, warp);
    #pragma unroll
    for (int i = 0; i < 3; i++){
      int v = warp*3 + i;
      if (v < NV){
        const float* tlrow = P.tl_table   + sidx[v]    * NC;
        const float* ltrow = P.lane_table + sidx[NV+v] * NC;
        #pragma unroll
        for (int j = 0; j < 4; j++){
          int c = lane + 32*j;
          fT[c*AP20 + v] = f2sum(acc[i][j]) + P.ch2b[c] + tlrow[c] + ltrow[c];
        }
      }
    }
  }
  __syncthreads();

  // ----- token expansion: 20 -> 64 -----
  stage_tokW(wb0, P.tk1w, NV, AP20, tid);
  stage_tokW(wb1, P.tk2w, NT, AP64, tid);
  __syncthreads();
  {
    u64 acc[8][4]; zero_acc8<8>(acc);
    tok_gemm<10, AP20, AP20>(fT, wb0, acc, lane, warp);
    __syncthreads();                       // all done reading fT (sf base) + h1
    #pragma unroll
    for (int p = 0; p < 8; p++){
      int u = warp*8 + p;
      float b = P.tk1b[u];
      #pragma unroll
      for (int j = 0; j < 4; j++)
        sy[(lane+32*j)*AP64 + u] = gelu_f(f2sum(acc[p][j]) + b);   // zT
    }
    __syncthreads();
    zero_acc8<8>(acc);
    tok_gemm<32, AP64, AP64>(sy, wb1, acc, lane, warp);
    #pragma unroll
    for (int p = 0; p < 8; p++){
      int t = warp*8 + p;
      float b = P.tk2b[t];
      #pragma unroll
      for (int j = 0; j < 4; j++)
        sf[t*NC + lane + 32*j] = f2sum(acc[p][j]) + b;
    }
  }
  __syncthreads();

  // ----- mixer blocks -----
  for (int d = 0; d < NDEPTH; d++){
    // LN1 -> yT (sy) ; stage token weights
    {
      float wg[4], bg[4];
      #pragma unroll
      for (int j = 0; j < 4; j++){
        wg[j] = P.bn1w[d*NC + lane + 32*j];
        bg[j] = P.bn1b[d*NC + lane + 32*j];
      }
      for (int t = warp; t < NT; t += 8){
        float v[4]; float s = 0.f, q = 0.f;
        #pragma unroll
        for (int j = 0; j < 4; j++){
          v[j] = sf[t*NC + lane + 32*j];
          s += v[j]; q += v[j]*v[j];
        }
        #pragma unroll
        for (int o = 16; o > 0; o >>= 1){
          s += __shfl_xor_sync(0xffffffffu, s, o);
          q += __shfl_xor_sync(0xffffffffu, q, o);
        }
        float m  = s * (1.f/NC);
        float var = q * (1.f/NC) - m*m;
        float rs = rsqrtf(var + 1e-5f);
        #pragma unroll
        for (int j = 0; j < 4; j++)
          sy[(lane+32*j)*AP64 + t] = (v[j]-m)*rs*wg[j] + bg[j];
      }
    }
    stage_tokW(wb0, P.bt1w + d*NT*NT, NT, AP64, tid);
    stage_tokW(wb1, P.bt2w + d*NT*NT, NT, AP64, tid);
    __syncthreads();

    // token mix
    {
      u64 acc[8][4]; zero_acc8<8>(acc);
      tok_gemm<32, AP64, AP64>(sy, wb0, acc, lane, warp);
      __syncthreads();                     // all reads of yT done before zT overwrite
      #pragma unroll
      for (int p = 0; p < 8; p++){
        int u = warp*8 + p;
        float b = P.bt1b[d*NT + u];
        #pragma unroll
        for (int j = 0; j < 4; j++)
          sy[(lane+32*j)*AP64 + u] = gelu_f(f2sum(acc[p][j]) + b);  // zT
      }
      __syncthreads();
      zero_acc8<8>(acc);
      tok_gemm<32, AP64, AP64>(sy, wb1, acc, lane, warp);
      #pragma unroll
      for (int p = 0; p < 8; p++){
        int t = warp*8 + p;
        float b = P.bt2b[d*NT + t];
        #pragma unroll
        for (int j = 0; j < 4; j++)
          sf[t*NC + lane + 32*j] += f2sum(acc[p][j]) + b;           // residual
      }
    }
    __syncthreads();

    // LN2 -> sy natural [t][c]
    {
      float wg[4], bg[4];
      #pragma unroll
      for (int j = 0; j < 4; j++){
        wg[j] = P.bn2w[d*NC + lane + 32*j];
        bg[j] = P.bn2b[d*NC + lane + 32*j];
      }
      for (int t = warp; t < NT; t += 8){
        float v[4]; float s = 0.f, q = 0.f;
        #pragma unroll
        for (int j = 0; j < 4; j++){
          v[j] = sf[t*NC + lane + 32*j];
          s += v[j]; q += v[j]*v[j];
        }
        #pragma unroll
        for (int o = 16; o > 0; o >>= 1){
          s += __shfl_xor_sync(0xffffffffu, s, o);
          q += __shfl_xor_sync(0xffffffffu, q, o);
        }
        float m  = s * (1.f/NC);
        float var = q * (1.f/NC) - m*m;
        float rs = rsqrtf(var + 1e-5f);
        #pragma unroll
        for (int j = 0; j < 4; j++)
          sy[t*NC + lane + 32*j] = (v[j]-m)*rs*wg[j] + bg[j];
      }
    }
    __syncthreads();

    // channel mix C1: h = gelu(y2 @ Wc1 + b1) -> sy (overwrite after full acc)
    {
      u64 acc[8][4]; zero_acc8<8>(acc);
      chan_gemm_full<8>(sy, P.bc1w + d*NC*NC, acc, wb0, wb1, tid, lane, warp);
      #pragma unroll
      for (int p = 0; p < 8; p++){
        int t = warp*8 + p;
        #pragma unroll
        for (int j = 0; j < 4; j++){
          int jj = lane + 32*j;
          sy[t*NC + jj] = gelu_f(f2sum(acc[p][j]) + P.bc1b[d*NC + jj]);
        }
      }
      __syncthreads();
      // channel mix C2: f += h @ Wc2 + b2
      zero_acc8<8>(acc);
      chan_gemm_full<8>(sy, P.bc2w + d*NC*NC, acc, wb0, wb1, tid, lane, warp);
      #pragma unroll
      for (int p = 0; p < 8; p++){
        int t = warp*8 + p;
        #pragma unroll
        for (int j = 0; j < 4; j++){
          int c = lane + 32*j;
          sf[t*NC + c] += f2sum(acc[p][j]) + P.bc2b[d*NC + c];
        }
      }
    }
    __syncthreads();
  }

  // ----- epilogue: token mean, LN, emb MLP -----
  {
    int c  = tid & 127;
    int hf = tid >> 7;
    float ps = 0.f;
    #pragma unroll 8
    for (int t = hf*32; t < hf*32 + 32; t++) ps += sf[t*NC + c];
    sy[hf*128 + c] = ps;
  }
  __syncthreads();
  float fm = 0.f;
  if (tid < NC){
    fm = (sy[tid] + sy[128 + tid]) * (1.f/NT);
    float s = fm, q = fm*fm;
    #pragma unroll
    for (int o = 16; o > 0; o >>= 1){
      s += __shfl_xor_sync(0xffffffffu, s, o);
      q += __shfl_xor_sync(0xffffffffu, q, o);
    }
    if (lane == 0){ sred[warp] = s; sred[4+warp] = q; }
  }
  __syncthreads();
  if (tid < NC){
    float s = sred[0]+sred[1]+sred[2]+sred[3];
    float q = sred[4]+sred[5]+sred[6]+sred[7];
    float m  = s * (1.f/NC);
    float var = q * (1.f/NC) - m*m;
    float rs = rsqrtf(var + 1e-5f);
    sy[256 + tid] = (fm - m)*rs*P.nw[tid] + P.nb[tid];
  }
  __syncthreads();
  if (tid < NH){
    float a = P.e1b[tid];
    #pragma unroll 8
    for (int c = 0; c < NC; c++) a += sy[256 + c] * P.e1w[c*NH + tid];
    sy[512 + tid] = gelu_f(a);
  }
  __syncthreads();
  if (tid < NH){
    float o = P.e2b[tid];
    #pragma unroll 8
    for (int j = 0; j < NH; j++) o += sy[512 + j] * P.e2w[j*NH + tid];
    float valid = sidx[3*NV] ? 0.f : 1.f;
    P.out[(size_t)r * NH + tid] = o * valid;
  }
}

extern "C" void kernel_launch(void* const* d_in, const int* in_sizes, int n_in,
                              void* d_out, int out_size){
  (void)in_sizes; (void)n_in; (void)out_size;
  Params P;
  P.x         = (const float*)d_in[0];
  P.tl_table  = (const float*)d_in[1];
  P.lane_table= (const float*)d_in[2];
  P.ch1w = (const float*)d_in[3];  P.ch1b = (const float*)d_in[4];
  P.ch2w = (const float*)d_in[5];  P.ch2b = (const float*)d_in[6];
  P.tk1w = (const float*)d_in[7];  P.tk1b = (const float*)d_in[8];
  P.tk2w = (const float*)d_in[9];  P.tk2b = (const float*)d_in[10];
  P.bn1w = (const float*)d_in[11]; P.bn1b = (const float*)d_in[12];
  P.bt1w = (const float*)d_in[13]; P.bt1b = (const float*)d_in[14];
  P.bt2w = (const float*)d_in[15]; P.bt2b = (const float*)d_in[16];
  P.bn2w = (const float*)d_in[17]; P.bn2b = (const float*)d_in[18];
  P.bc1w = (const float*)d_in[19]; P.bc1b = (const float*)d_in[20];
  P.bc2w = (const float*)d_in[21]; P.bc2b = (const float*)d_in[22];
  P.nw   = (const float*)d_in[23]; P.nb   = (const float*)d_in[24];
  P.e1w  = (const float*)d_in[25]; P.e1b  = (const float*)d_in[26];
  P.e2w  = (const float*)d_in[27]; P.e2b  = (const float*)d_in[28];

  const int NRows = 8192;
  float* ob = (float*)d_out;
  P.out      = ob;
  P.mask_out = ob + (size_t)NRows*NH;
  P.pos_out  = ob + (size_t)NRows*NH + NRows;

  cudaFuncSetAttribute(lane_fusion_kernel,
                       cudaFuncAttributeMaxDynamicSharedMemorySize, SMEM_BYTES);
  lane_fusion_kernel<<<NRows, 256, SMEM_BYTES>>>(P);
}

// round 6
// speedup vs baseline: 1.6365x; 1.2944x over previous
#include <cuda_runtime.h>
#include <math.h>

#define NV 20
#define NC 128
#define NT 64
#define NH 192
#define N_TL 9
#define N_LT 20
#define NDEPTH 3

// shared memory layout (floats) — all natural [row][128] layouts
#define OFF_SF   0        // 8192 : state f[64][128]
#define OFF_SY   8192     // 8192 : scratch y/z/h [64][128] (h1 uses rows 0..23)
#define OFF_W0   16384    // 4096 : weight tile buffer 0
#define OFF_W1   20480    // 4096 : weight tile buffer 1
#define OFF_SG   24576    // 96
#define OFF_SRED 24672    // 16
#define OFF_SIDX 24688    // 64 ints
#define SMEM_FLOATS 24752
#define SMEM_BYTES (SMEM_FLOATS*4)

typedef unsigned long long u64;
union F2U { float2 f2; u64 u; float f[2]; };

struct Params {
  const float* x;
  const float* tl_table; const float* lane_table;
  const float* ch1w; const float* ch1b; const float* ch2w; const float* ch2b;
  const float* tk1w; const float* tk1b; const float* tk2w; const float* tk2b;
  const float* bn1w; const float* bn1b;
  const float* bt1w; const float* bt1b; const float* bt2w; const float* bt2b;
  const float* bn2w; const float* bn2b;
  const float* bc1w; const float* bc1b; const float* bc2w; const float* bc2b;
  const float* nw;  const float* nb;
  const float* e1w; const float* e1b; const float* e2w; const float* e2b;
  float* out; float* mask_out; float* pos_out;
};

__device__ __forceinline__ float gelu_f(float v){
  return 0.5f * v * (1.0f + erff(v * 0.70710678118654752440f));
}
__device__ __forceinline__ u64 lds_f2(const float* p){
  F2U t; t.f2 = *reinterpret_cast<const float2*>(p); return t.u;
}
__device__ __forceinline__ u64 rep2(float v){
  u64 r; asm("mov.b64 %0, {%1, %1};" : "=l"(r) : "f"(v)); return r;
}
__device__ __forceinline__ void ffma2(u64& d, u64 a, u64 b){
  asm("fma.rn.f32x2 %0, %1, %2, %0;" : "+l"(d) : "l"(a), "l"(b));
}

// ---------------- token-type GEMM ----------------
// out[u][c] = sum_{k<K} A[k][c] * W[k][u]
// f2 halves = u-pair: acc[p][j] holds (out[warp*8+2p][c], out[warp*8+2p+1][c]), c=lane+32j
// A natural [K][128] in smem; W natural [K][64] in smem.
template<int K>
__device__ __forceinline__ void tok_gemm(const float* __restrict__ A,
                                         const float* __restrict__ W,
                                         u64 acc[4][4], int lane, int warp){
  const float* wp = W + warp*8;
  const float* ap = A + lane;
  #pragma unroll 4
  for (int k = 0; k < K; k++){
    u64 w[4];
    #pragma unroll
    for (int p = 0; p < 4; p++) w[p] = lds_f2(wp + k*64 + 2*p);   // broadcast .64
    u64 a[4];
    #pragma unroll
    for (int j = 0; j < 4; j++) a[j] = rep2(ap[k*NC + 32*j]);     // conflict-free .32
    #pragma unroll
    for (int p = 0; p < 4; p++)
      #pragma unroll
      for (int j = 0; j < 4; j++) ffma2(acc[p][j], w[p], a[j]);
  }
}

// ---------------- channel-type GEMM tile (32 c's) ----------------
// out[t][j] = sum_c A[t][c] * W[c][j]
// f2 halves = j-pair: acc[i][j'] holds (out[t][2*(lane+32j')], out[t][2*(lane+32j')+1]),
// t = warp*I + i.  A natural [rows][128]; wb tile natural [32][128] (c-major rows).
template<int I>
__device__ __forceinline__ void chan_tile(const float* __restrict__ A,
                                          const float* __restrict__ wb,
                                          u64 acc[I][2], int lane, int warp, int c0){
  const float* wl = wb + 2*lane;
  #pragma unroll 2
  for (int c4 = 0; c4 < 8; c4++){
    float4 a4[I];
    #pragma unroll
    for (int i = 0; i < I; i++)
      a4[i] = *reinterpret_cast<const float4*>(A + (warp*I + i)*NC + c0 + 4*c4);  // bcast .128
    #pragma unroll
    for (int r = 0; r < 4; r++){
      int cc = 4*c4 + r;
      u64 w0 = lds_f2(wl + cc*NC);        // strided f2, conflict-free
      u64 w1 = lds_f2(wl + cc*NC + 64);
      #pragma unroll
      for (int i = 0; i < I; i++){
        float av = (r==0) ? a4[i].x : (r==1) ? a4[i].y : (r==2) ? a4[i].z : a4[i].w;
        u64 a = rep2(av);
        ffma2(acc[i][0], a, w0);
        ffma2(acc[i][1], a, w1);
      }
    }
  }
}

// full K=128 channel GEMM, ping-pong contiguous-staged 32x128 weight tiles
template<int I>
__device__ void chan_gemm_full(const float* __restrict__ A, const float* __restrict__ gw,
                               u64 acc[I][2], float* wb0, float* wb1, int tid,
                               int lane, int warp){
  const float4* g4 = reinterpret_cast<const float4*>(gw);
  float4 pre[4];
  #pragma unroll
  for (int q = 0; q < 4; q++) pre[q] = g4[tid + 256*q];
  {
    float4* s4 = reinterpret_cast<float4*>(wb0);
    #pragma unroll
    for (int q = 0; q < 4; q++) s4[tid + 256*q] = pre[q];
  }
  __syncthreads();
  #pragma unroll
  for (int t = 0; t < 4; t++){
    if (t < 3){
      #pragma unroll
      for (int q = 0; q < 4; q++) pre[q] = g4[(t+1)*1024 + tid + 256*q];
    }
    chan_tile<I>(A, (t & 1) ? wb1 : wb0, acc, lane, warp, t*32);
    if (t < 3){
      float4* s4 = reinterpret_cast<float4*>(((t+1) & 1) ? wb1 : wb0);
      #pragma unroll
      for (int q = 0; q < 4; q++) s4[tid + 256*q] = pre[q];
    }
    __syncthreads();
  }
}

// contiguous stage of n4 float4s
__device__ __forceinline__ void stage_cp(float* dst, const float* __restrict__ src,
                                         int n4, int tid){
  const float4* g4 = reinterpret_cast<const float4*>(src);
  float4* s4 = reinterpret_cast<float4*>(dst);
  for (int i = tid; i < n4; i += 256) s4[i] = g4[i];
}

template<int A0, int A1>
__device__ __forceinline__ void zero_acc(u64 acc[A0][A1]){
  #pragma unroll
  for (int i = 0; i < A0; i++)
    #pragma unroll
    for (int j = 0; j < A1; j++) acc[i][j] = 0ull;
}

__global__ void __launch_bounds__(256, 2)
lane_fusion_kernel(Params P){
  extern __shared__ float smem[];
  float* sf  = smem + OFF_SF;
  float* sy  = smem + OFF_SY;
  float* wb0 = smem + OFF_W0;
  float* wb1 = smem + OFF_W1;
  float* sg  = smem + OFF_SG;
  float* sred= smem + OFF_SRED;
  int*   sidx= (int*)(smem + OFF_SIDX);

  const int tid  = threadIdx.x;
  const int lane = tid & 31;
  const int warp = tid >> 5;
  const int r    = blockIdx.x;
  const float* xr = P.x + (size_t)r * (NV*5);

  // ----- preprocess -----
  if (tid < NV){
    float x0 = xr[tid*5+0], x1 = xr[tid*5+1], hg = xr[tid*5+2];
    float x3 = xr[tid*5+3], x4 = xr[tid*5+4];
    float ch = cosf(hg), sh = sinf(hg);
    sg[tid*4+0] = x0; sg[tid*4+1] = x1; sg[tid*4+2] = ch; sg[tid*4+3] = sh;
    int tl = (int)x3; tl = tl < 0 ? 0 : (tl > N_TL-1 ? N_TL-1 : tl);
    int lt = (int)x4; lt = lt < 0 ? 0 : (lt > N_LT-1 ? N_LT-1 : lt);
    sidx[tid]      = tl;
    sidx[NV+tid]   = lt;
    sidx[2*NV+tid] = (x0==0.f && x1==0.f && ch==0.f && sh==0.f) ? 1 : 0;
  }
  if (tid < 5){
    float mid = xr[(NV/2)*5 + tid];
    float sc = (tid==3) ? (1.f/(N_TL-1)) : ((tid==4) ? (1.f/(N_LT-1)) : 1.f);
    P.pos_out[(size_t)r*5 + tid] = mid * sc;
  }
  __syncthreads();
  if (tid == 0){
    int mp = 1;
    for (int v = 0; v < NV; v++) mp &= sidx[2*NV+v];
    sidx[3*NV] = mp;
    P.mask_out[r] = mp ? 1.f : 0.f;
  }

  // ----- stage 1a: h1[v][c] = gelu(g @ ch1w + b) -> sy rows 0..19; rows 20..23 zero
  {
    int c  = tid & 127;
    int hf = tid >> 7;
    float w0 = P.ch1w[0*NC + c], w1 = P.ch1w[1*NC + c];
    float w2 = P.ch1w[2*NC + c], w3 = P.ch1w[3*NC + c];
    float b  = P.ch1b[c];
    #pragma unroll
    for (int v = hf*10; v < hf*10 + 10; v++){
      float a = b + sg[v*4+0]*w0 + sg[v*4+1]*w1 + sg[v*4+2]*w2 + sg[v*4+3]*w3;
      sy[v*NC + c] = gelu_f(a);
    }
    if (hf == 0){
      #pragma unroll
      for (int v = NV; v < 24; v++) sy[v*NC + c] = 0.f;
    }
  }
  __syncthreads();

  // ----- stage 1b: f0[v][c] = h1 @ ch2w + b + tables -> sf rows 0..19 (natural)
  {
    u64 acc[3][2]; zero_acc<3,2>(acc);
    chan_gemm_full<3>(sy, P.ch2w, acc, wb0, wb1, tid, lane, warp);
    #pragma unroll
    for (int i = 0; i < 3; i++){
      int v = warp*3 + i;
      if (v < NV){
        const float* tlrow = P.tl_table   + sidx[v]    * NC;
        const float* ltrow = P.lane_table + sidx[NV+v] * NC;
        #pragma unroll
        for (int jp = 0; jp < 2; jp++){
          int c = 2*(lane + 32*jp);
          F2U t; t.u = acc[i][jp];
          sf[v*NC + c]   = t.f[0] + P.ch2b[c]   + tlrow[c]   + ltrow[c];
          sf[v*NC + c+1] = t.f[1] + P.ch2b[c+1] + tlrow[c+1] + ltrow[c+1];
        }
      }
    }
  }
  __syncthreads();

  // ----- token expansion: 20 -> 64 -----
  stage_cp(wb0, P.tk1w, (NV*NT)/4, tid);
  stage_cp(wb1, P.tk2w, (NT*NT)/4, tid);
  __syncthreads();
  {
    u64 acc[4][4]; zero_acc<4,4>(acc);
    tok_gemm<NV>(sf, wb0, acc, lane, warp);
    __syncthreads();
    #pragma unroll
    for (int p = 0; p < 4; p++){
      int u0 = warp*8 + 2*p;
      float b0 = P.tk1b[u0], b1 = P.tk1b[u0+1];
      #pragma unroll
      for (int j = 0; j < 4; j++){
        int c = lane + 32*j;
        F2U t; t.u = acc[p][j];
        sy[u0*NC + c]     = gelu_f(t.f[0] + b0);
        sy[(u0+1)*NC + c] = gelu_f(t.f[1] + b1);
      }
    }
    __syncthreads();
    zero_acc<4,4>(acc);
    tok_gemm<NT>(sy, wb1, acc, lane, warp);
    #pragma unroll
    for (int p = 0; p < 4; p++){
      int t0 = warp*8 + 2*p;
      float b0 = P.tk2b[t0], b1 = P.tk2b[t0+1];
      #pragma unroll
      for (int j = 0; j < 4; j++){
        int c = lane + 32*j;
        F2U t; t.u = acc[p][j];
        sf[t0*NC + c]     = t.f[0] + b0;
        sf[(t0+1)*NC + c] = t.f[1] + b1;
      }
    }
  }
  __syncthreads();

  // ----- mixer blocks -----
  for (int d = 0; d < NDEPTH; d++){
    // LN1 -> sy (natural)
    {
      float wg[4], bg[4];
      #pragma unroll
      for (int j = 0; j < 4; j++){
        wg[j] = P.bn1w[d*NC + lane + 32*j];
        bg[j] = P.bn1b[d*NC + lane + 32*j];
      }
      for (int t = warp; t < NT; t += 8){
        float v[4]; float s = 0.f, q = 0.f;
        #pragma unroll
        for (int j = 0; j < 4; j++){
          v[j] = sf[t*NC + lane + 32*j];
          s += v[j]; q += v[j]*v[j];
        }
        #pragma unroll
        for (int o = 16; o > 0; o >>= 1){
          s += __shfl_xor_sync(0xffffffffu, s, o);
          q += __shfl_xor_sync(0xffffffffu, q, o);
        }
        float m  = s * (1.f/NC);
        float var = q * (1.f/NC) - m*m;
        float rs = rsqrtf(var + 1e-5f);
        #pragma unroll
        for (int j = 0; j < 4; j++)
          sy[t*NC + lane + 32*j] = (v[j]-m)*rs*wg[j] + bg[j];
      }
    }
    stage_cp(wb0, P.bt1w + d*NT*NT, (NT*NT)/4, tid);
    stage_cp(wb1, P.bt2w + d*NT*NT, (NT*NT)/4, tid);
    __syncthreads();

    // token mix
    {
      u64 acc[4][4]; zero_acc<4,4>(acc);
      tok_gemm<NT>(sy, wb0, acc, lane, warp);
      __syncthreads();                 // all reads of y done before z overwrite
      #pragma unroll
      for (int p = 0; p < 4; p++){
        int u0 = warp*8 + 2*p;
        float b0 = P.bt1b[d*NT + u0], b1 = P.bt1b[d*NT + u0+1];
        #pragma unroll
        for (int j = 0; j < 4; j++){
          int c = lane + 32*j;
          F2U t; t.u = acc[p][j];
          sy[u0*NC + c]     = gelu_f(t.f[0] + b0);
          sy[(u0+1)*NC + c] = gelu_f(t.f[1] + b1);
        }
      }
      __syncthreads();
      zero_acc<4,4>(acc);
      tok_gemm<NT>(sy, wb1, acc, lane, warp);
      #pragma unroll
      for (int p = 0; p < 4; p++){
        int t0 = warp*8 + 2*p;
        float b0 = P.bt2b[d*NT + t0], b1 = P.bt2b[d*NT + t0+1];
        #pragma unroll
        for (int j = 0; j < 4; j++){
          int c = lane + 32*j;
          F2U t; t.u = acc[p][j];
          sf[t0*NC + c]     += t.f[0] + b0;
          sf[(t0+1)*NC + c] += t.f[1] + b1;
        }
      }
    }
    __syncthreads();

    // LN2 -> sy (natural)
    {
      float wg[4], bg[4];
      #pragma unroll
      for (int j = 0; j < 4; j++){
        wg[j] = P.bn2w[d*NC + lane + 32*j];
        bg[j] = P.bn2b[d*NC + lane + 32*j];
      }
      for (int t = warp; t < NT; t += 8){
        float v[4]; float s = 0.f, q = 0.f;
        #pragma unroll
        for (int j = 0; j < 4; j++){
          v[j] = sf[t*NC + lane + 32*j];
          s += v[j]; q += v[j]*v[j];
        }
        #pragma unroll
        for (int o = 16; o > 0; o >>= 1){
          s += __shfl_xor_sync(0xffffffffu, s, o);
          q += __shfl_xor_sync(0xffffffffu, q, o);
        }
        float m  = s * (1.f/NC);
        float var = q * (1.f/NC) - m*m;
        float rs = rsqrtf(var + 1e-5f);
        #pragma unroll
        for (int j = 0; j < 4; j++)
          sy[t*NC + lane + 32*j] = (v[j]-m)*rs*wg[j] + bg[j];
      }
    }
    __syncthreads();

    // channel mix C1: h = gelu(y2 @ Wc1 + b1) -> sy (after full acc)
    {
      u64 acc[8][2]; zero_acc<8,2>(acc);
      chan_gemm_full<8>(sy, P.bc1w + d*NC*NC, acc, wb0, wb1, tid, lane, warp);
      #pragma unroll
      for (int i = 0; i < 8; i++){
        int t = warp*8 + i;
        #pragma unroll
        for (int jp = 0; jp < 2; jp++){
          int c = 2*(lane + 32*jp);
          F2U v; v.u = acc[i][jp];
          float2 o;
          o.x = gelu_f(v.f[0] + P.bc1b[d*NC + c]);
          o.y = gelu_f(v.f[1] + P.bc1b[d*NC + c+1]);
          *reinterpret_cast<float2*>(sy + t*NC + c) = o;
        }
      }
      __syncthreads();
      // channel mix C2: f += h @ Wc2 + b2
      zero_acc<8,2>(acc);
      chan_gemm_full<8>(sy, P.bc2w + d*NC*NC, acc, wb0, wb1, tid, lane, warp);
      #pragma unroll
      for (int i = 0; i < 8; i++){
        int t = warp*8 + i;
        #pragma unroll
        for (int jp = 0; jp < 2; jp++){
          int c = 2*(lane + 32*jp);
          F2U v; v.u = acc[i][jp];
          float2 o = *reinterpret_cast<float2*>(sf + t*NC + c);
          o.x += v.f[0] + P.bc2b[d*NC + c];
          o.y += v.f[1] + P.bc2b[d*NC + c+1];
          *reinterpret_cast<float2*>(sf + t*NC + c) = o;
        }
      }
    }
    __syncthreads();
  }

  // ----- epilogue: token mean, LN, emb MLP -----
  {
    int c  = tid & 127;
    int hf = tid >> 7;
    float ps = 0.f;
    #pragma unroll 8
    for (int t = hf*32; t < hf*32 + 32; t++) ps += sf[t*NC + c];
    sy[hf*128 + c] = ps;
  }
  __syncthreads();
  float fm = 0.f;
  if (tid < NC){
    fm = (sy[tid] + sy[128 + tid]) * (1.f/NT);
    float s = fm, q = fm*fm;
    #pragma unroll
    for (int o = 16; o > 0; o >>= 1){
      s += __shfl_xor_sync(0xffffffffu, s, o);
      q += __shfl_xor_sync(0xffffffffu, q, o);
    }
    if (lane == 0){ sred[warp] = s; sred[4+warp] = q; }
  }
  __syncthreads();
  if (tid < NC){
    float s = sred[0]+sred[1]+sred[2]+sred[3];
    float q = sred[4]+sred[5]+sred[6]+sred[7];
    float m  = s * (1.f/NC);
    float var = q * (1.f/NC) - m*m;
    float rs = rsqrtf(var + 1e-5f);
    sy[256 + tid] = (fm - m)*rs*P.nw[tid] + P.nb[tid];
  }
  __syncthreads();
  if (tid < NH){
    float a = P.e1b[tid];
    #pragma unroll 8
    for (int c = 0; c < NC; c++) a += sy[256 + c] * P.e1w[c*NH + tid];
    sy[512 + tid] = gelu_f(a);
  }
  __syncthreads();
  if (tid < NH){
    float o = P.e2b[tid];
    #pragma unroll 8
    for (int j = 0; j < NH; j++) o += sy[512 + j] * P.e2w[j*NH + tid];
    float valid = sidx[3*NV] ? 0.f : 1.f;
    P.out[(size_t)r * NH + tid] = o * valid;
  }
}

extern "C" void kernel_launch(void* const* d_in, const int* in_sizes, int n_in,
                              void* d_out, int out_size){
  (void)in_sizes; (void)n_in; (void)out_size;
  Params P;
  P.x         = (const float*)d_in[0];
  P.tl_table  = (const float*)d_in[1];
  P.lane_table= (const float*)d_in[2];
  P.ch1w = (const float*)d_in[3];  P.ch1b = (const float*)d_in[4];
  P.ch2w = (const float*)d_in[5];  P.ch2b = (const float*)d_in[6];
  P.tk1w = (const float*)d_in[7];  P.tk1b = (const float*)d_in[8];
  P.tk2w = (const float*)d_in[9];  P.tk2b = (const float*)d_in[10];
  P.bn1w = (const float*)d_in[11]; P.bn1b = (const float*)d_in[12];
  P.bt1w = (const float*)d_in[13]; P.bt1b = (const float*)d_in[14];
  P.bt2w = (const float*)d_in[15]; P.bt2b = (const float*)d_in[16];
  P.bn2w = (const float*)d_in[17]; P.bn2b = (const float*)d_in[18];
  P.bc1w = (const float*)d_in[19]; P.bc1b = (const float*)d_in[20];
  P.bc2w = (const float*)d_in[21]; P.bc2b = (const float*)d_in[22];
  P.nw   = (const float*)d_in[23]; P.nb   = (const float*)d_in[24];
  P.e1w  = (const float*)d_in[25]; P.e1b  = (const float*)d_in[26];
  P.e2w  = (const float*)d_in[27]; P.e2b  = (const float*)d_in[28];

  const int NRows = 8192;
  float* ob = (float*)d_out;
  P.out      = ob;
  P.mask_out = ob + (size_t)NRows*NH;
  P.pos_out  = ob + (size_t)NRows*NH + NRows;

  cudaFuncSetAttribute(lane_fusion_kernel,
                       cudaFuncAttributeMaxDynamicSharedMemorySize, SMEM_BYTES);
  lane_fusion_kernel<<<NRows, 256, SMEM_BYTES>>>(P);
}